// round 3
// baseline (speedup 1.0000x reference)
#include <cuda_runtime.h>
#include <cstdint>

// TCNN_INR: instant-ngp hash encoding (12 levels x 4 features) + MLP 48->128->128->1
// One thread = one pixel, fully fused: encoding accumulates straight into the
// 128 layer-1 register accumulators; layer2+w3 fused with 8-wide output chunks.
// Weights staged in shared memory (uniform LDS.128 broadcasts).

#define PRIME_Y 2654435761u
#define HASH_MASK 0xFFFFFu

// scale = 16*1.5^l - 1 (exact in fp32), res = ceil(scale)+1
__constant__ float    c_scale[12] = {15.0f, 23.0f, 35.0f, 53.0f, 80.0f, 120.5f,
                                     181.25f, 272.375f, 409.0625f, 614.09375f,
                                     921.640625f, 1382.9609375f};
__constant__ unsigned c_res[12]   = {16u, 24u, 36u, 54u, 81u, 122u,
                                     183u, 274u, 411u, 616u, 923u, 1384u};

static const int SMEM_FLOATS = 6144 + 16384 + 128;   // w1 + w2 + w3
static const int SMEM_BYTES  = SMEM_FLOATS * 4;      // 90624 B -> 2 blocks/SM

__global__ __launch_bounds__(128, 2)
void tcnn_inr_kernel(const float* __restrict__ table,
                     const float* __restrict__ w1,
                     const float* __restrict__ w2,
                     const float* __restrict__ w3,
                     float* __restrict__ out)
{
    extern __shared__ float smem[];
    float* w1_s = smem;                    // [48][128]
    float* w2_s = smem + 6144;             // [128][128]
    float* w3_s = smem + 6144 + 16384;     // [128]

    const int tid = threadIdx.x;

    // Stage weights (vectorized, coalesced)
    {
        float4*       d1 = (float4*)w1_s;
        const float4* s1 = (const float4*)w1;
        #pragma unroll 4
        for (int i = tid; i < 1536; i += 128) d1[i] = s1[i];
        float4*       d2 = (float4*)w2_s;
        const float4* s2 = (const float4*)w2;
        #pragma unroll 4
        for (int i = tid; i < 4096; i += 128) d2[i] = s2[i];
        float4*       d3 = (float4*)w3_s;
        const float4* s3 = (const float4*)w3;
        for (int i = tid; i < 32; i += 128) d3[i] = s3[i];
    }
    __syncthreads();

    const int pix = blockIdx.x * 128 + tid;
    const float fx = (float)(pix & 1023) * (1.0f / 1023.0f);
    const float fy = (float)(pix >> 10)  * (1.0f / 1023.0f);

    // Layer-1 accumulators (h1 = enc @ w1), kept in registers the whole time.
    float h[128];
    #pragma unroll
    for (int j = 0; j < 128; j++) h[j] = 0.0f;

    // ---- Encoding fused with layer 1 ----
    #pragma unroll 1
    for (int l = 0; l < 12; l++) {
        const float    s   = c_scale[l];
        const unsigned res = c_res[l];

        float posx = fmaf(fx, s, 0.5f);
        float posy = fmaf(fy, s, 0.5f);
        float fpx = floorf(posx), fpy = floorf(posy);
        float wx = posx - fpx,    wy = posy - fpy;
        unsigned px0 = (unsigned)fpx, py0 = (unsigned)fpy;
        unsigned px1 = min(px0 + 1u, res - 1u);
        unsigned py1 = min(py0 + 1u, res - 1u);

        unsigned i00, i10, i01, i11;
        if (l < 11) {                       // dense levels (res*res <= 2^20)
            i00 = px0 + py0 * res;  i10 = px1 + py0 * res;
            i01 = px0 + py1 * res;  i11 = px1 + py1 * res;
        } else {                            // hashed level
            unsigned hy0 = py0 * PRIME_Y;
            unsigned hy1 = py1 * PRIME_Y;
            i00 = (px0 ^ hy0) & HASH_MASK;  i10 = (px1 ^ hy0) & HASH_MASK;
            i01 = (px0 ^ hy1) & HASH_MASK;  i11 = (px1 ^ hy1) & HASH_MASK;
        }

        const float4* tb = (const float4*)table + ((size_t)l << 20);
        float4 f00 = __ldg(tb + i00);
        float4 f10 = __ldg(tb + i10);
        float4 f01 = __ldg(tb + i01);
        float4 f11 = __ldg(tb + i11);

        float w00 = (1.0f - wx) * (1.0f - wy);
        float w10 = wx * (1.0f - wy);
        float w01 = (1.0f - wx) * wy;
        float w11 = wx * wy;

        float e0 = f00.x*w00 + f10.x*w10 + f01.x*w01 + f11.x*w11;
        float e1 = f00.y*w00 + f10.y*w10 + f01.y*w01 + f11.y*w11;
        float e2 = f00.z*w00 + f10.z*w10 + f01.z*w01 + f11.z*w11;
        float e3 = f00.w*w00 + f10.w*w10 + f01.w*w01 + f11.w*w11;

        // h[j] += e0*w1[4l+0][j] + e1*w1[4l+1][j] + e2*w1[4l+2][j] + e3*w1[4l+3][j]
        const float4* wr0 = (const float4*)(w1_s + (l*4 + 0) * 128);
        const float4* wr1 = (const float4*)(w1_s + (l*4 + 1) * 128);
        const float4* wr2 = (const float4*)(w1_s + (l*4 + 2) * 128);
        const float4* wr3 = (const float4*)(w1_s + (l*4 + 3) * 128);
        #pragma unroll
        for (int j4 = 0; j4 < 32; j4++) {
            float4 a = wr0[j4], b = wr1[j4], c = wr2[j4], d = wr3[j4];
            h[4*j4+0] += e0*a.x + e1*b.x + e2*c.x + e3*d.x;
            h[4*j4+1] += e0*a.y + e1*b.y + e2*c.y + e3*d.y;
            h[4*j4+2] += e0*a.z + e1*b.z + e2*c.z + e3*d.z;
            h[4*j4+3] += e0*a.w + e1*b.w + e2*c.w + e3*d.w;
        }
    }

    // ReLU after layer 1
    #pragma unroll
    for (int j = 0; j < 128; j++) h[j] = fmaxf(h[j], 0.0f);

    // ---- Layer 2 fused with w3 (8 outputs at a time) ----
    float out_acc = 0.0f;
    #pragma unroll 1
    for (int jc = 0; jc < 16; jc++) {
        float acc[8];
        #pragma unroll
        for (int r = 0; r < 8; r++) acc[r] = 0.0f;
        const float* wb = w2_s + jc * 8;
        #pragma unroll
        for (int k = 0; k < 128; k++) {
            float4 wa = *(const float4*)(wb + k * 128);
            float4 wc = *(const float4*)(wb + k * 128 + 4);
            float hv = h[k];
            acc[0] += hv * wa.x;  acc[1] += hv * wa.y;
            acc[2] += hv * wa.z;  acc[3] += hv * wa.w;
            acc[4] += hv * wc.x;  acc[5] += hv * wc.y;
            acc[6] += hv * wc.z;  acc[7] += hv * wc.w;
        }
        float4 w3a = *(const float4*)(w3_s + jc * 8);
        float4 w3b = *(const float4*)(w3_s + jc * 8 + 4);
        out_acc += fmaxf(acc[0], 0.0f) * w3a.x + fmaxf(acc[1], 0.0f) * w3a.y
                 + fmaxf(acc[2], 0.0f) * w3a.z + fmaxf(acc[3], 0.0f) * w3a.w
                 + fmaxf(acc[4], 0.0f) * w3b.x + fmaxf(acc[5], 0.0f) * w3b.y
                 + fmaxf(acc[6], 0.0f) * w3b.z + fmaxf(acc[7], 0.0f) * w3b.w;
    }

    out[pix] = out_acc;
}

extern "C" void kernel_launch(void* const* d_in, const int* in_sizes, int n_in,
                              void* d_out, int out_size)
{
    // Identify inputs by element count (robust to H/W scalar placement):
    // table: 12*2^20*4 = 50331648, w1: 48*128 = 6144, w2: 128*128 = 16384, w3: 128
    const float *table = nullptr, *w1 = nullptr, *w2 = nullptr, *w3 = nullptr;
    for (int i = 0; i < n_in; i++) {
        switch (in_sizes[i]) {
            case 50331648: table = (const float*)d_in[i]; break;
            case 6144:     w1    = (const float*)d_in[i]; break;
            case 16384:    w2    = (const float*)d_in[i]; break;
            case 128:      w3    = (const float*)d_in[i]; break;
            default: break;
        }
    }

    cudaFuncSetAttribute(tcnn_inr_kernel,
                         cudaFuncAttributeMaxDynamicSharedMemorySize, SMEM_BYTES);
    tcnn_inr_kernel<<<(1024 * 1024) / 128, 128, SMEM_BYTES>>>(
        table, w1, w2, w3, (float*)d_out);
}

// round 5
// speedup vs baseline: 1.8784x; 1.8784x over previous
#include <cuda_runtime.h>
#include <cstdint>

// TCNN_INR via legacy mma.sync (tf32 HMMA, generic PTX — tcgen05 unavailable
// because the harness compiles through compute_103 non-'a' PTX).
//
// CTA = 256 threads / 128 pixels. Encoding: 2 threads per pixel (6 levels each)
// -> E[128x48] in SMEM (tf32, k-permuted). Layer1/Layer2: warp-level
// m16n8k8.tf32 MMAs with weights REGISTER-RESIDENT (each warp owns a 16-col
// N-slice, so B fragments load once). A fragments come from SMEM as LDS.64
// thanks to a k-interleave permutation. Layer3: per-warp partials + smem reduce.

#define PRIME_Y   2654435761u
#define HASH_MASK 0xFFFFFu

__constant__ float    c_scale[12] = {15.0f, 23.0f, 35.0f, 53.0f, 80.0f, 120.5f,
                                     181.25f, 272.375f, 409.0625f, 614.09375f,
                                     921.640625f, 1382.9609375f};
__constant__ unsigned c_res[12]   = {16u, 24u, 36u, 54u, 81u, 122u,
                                     183u, 274u, 411u, 616u, 923u, 1384u};

// k-interleave permutation within groups of 8: j -> [0,4,1,5,2,6,3,7] position,
// so that (k, k+4) fragment pairs land on adjacent storage columns (LDS.64).
__device__ __forceinline__ int pcol(int k) {
    int j = k & 7;
    return (k & ~7) | ((j < 4) ? (j << 1) : (((j - 4) << 1) | 1));
}

__device__ __forceinline__ uint32_t f2tf32(float f) {
    uint32_t b;
    asm("cvt.rna.tf32.f32 %0, %1;" : "=r"(b) : "f"(f));
    return b;
}

__device__ __forceinline__ void mma8(float& d0, float& d1, float& d2, float& d3,
                                     uint32_t a0, uint32_t a1, uint32_t a2, uint32_t a3,
                                     uint32_t b0, uint32_t b1) {
    asm volatile("mma.sync.aligned.m16n8k8.row.col.f32.tf32.tf32.f32 "
                 "{%0,%1,%2,%3}, {%4,%5,%6,%7}, {%8,%9}, {%0,%1,%2,%3};"
                 : "+f"(d0), "+f"(d1), "+f"(d2), "+f"(d3)
                 : "r"(a0), "r"(a1), "r"(a2), "r"(a3), "r"(b0), "r"(b1));
}

// SMEM float offsets (strides padded for bank spread)
#define E_STRIDE  52     // 48 cols + pad
#define W1_STRIDE 52
#define W2_STRIDE 132    // 128 cols + pad
#define H1_STRIDE 132
#define E_OFF   0
#define W1_OFF  (E_OFF  + 128 * E_STRIDE)    // 6656
#define W2_OFF  (W1_OFF + 128 * W1_STRIDE)   // 13312
#define H1_OFF  (W2_OFF + 128 * W2_STRIDE)   // 30208
#define P_OFF   (H1_OFF + 128 * H1_STRIDE)   // 47104
#define W3_OFF  (P_OFF  + 8 * 128)           // 48128
#define SMEM_FLOATS (W3_OFF + 128)           // 48256
#define SMEM_BYTES  (SMEM_FLOATS * 4)        // 193024

__global__ void __launch_bounds__(256, 1)
tcnn_hmma_kernel(const float* __restrict__ table,
                 const float* __restrict__ w1,
                 const float* __restrict__ w2,
                 const float* __restrict__ w3,
                 float* __restrict__ out)
{
    extern __shared__ float sm[];
    float*    E   = sm + E_OFF;
    float*    W1s = sm + W1_OFF;
    float*    W2s = sm + W2_OFF;
    float*    H1  = sm + H1_OFF;
    float*    P   = sm + P_OFF;
    float*    w3s = sm + W3_OFF;
    uint32_t* Eu  = (uint32_t*)E;
    uint32_t* W1u = (uint32_t*)W1s;
    uint32_t* W2u = (uint32_t*)W2s;
    uint32_t* H1u = (uint32_t*)H1;

    const int tid  = threadIdx.x;
    const int lane = tid & 31;
    const int warp = tid >> 5;
    const int g    = lane >> 2;   // groupID
    const int t    = lane & 3;    // threadID_in_group

    // ---- Stage weights (transposed to [n][k], tf32, k-permuted) ----
    #pragma unroll 4
    for (int idx = tid; idx < 6144; idx += 256) {        // w1: [48][128] -> W1s[n][k]
        int k = idx >> 7, n = idx & 127;
        W1u[n * W1_STRIDE + pcol(k)] = f2tf32(w1[idx]);
    }
    #pragma unroll 4
    for (int idx = tid; idx < 16384; idx += 256) {       // w2: [128][128] -> W2s[n][k]
        int k = idx >> 7, n = idx & 127;
        W2u[n * W2_STRIDE + pcol(k)] = f2tf32(w2[idx]);
    }
    if (tid < 128) w3s[tid] = w3[tid];

    // ---- Hash encoding: 2 threads per pixel, 6 levels each -> E (tf32) ----
    {
        const int   lp    = tid & 127;
        const int   lbase = (tid >> 7) * 6;
        const int   pix   = blockIdx.x * 128 + lp;
        const float fx = (float)(pix & 1023) * (1.0f / 1023.0f);
        const float fy = (float)(pix >> 10)  * (1.0f / 1023.0f);
        uint32_t* Er = Eu + lp * E_STRIDE;

        #pragma unroll
        for (int li = 0; li < 6; li++) {
            const int      l   = lbase + li;
            const float    s   = c_scale[l];
            const unsigned res = c_res[l];
            float posx = fmaf(fx, s, 0.5f);
            float posy = fmaf(fy, s, 0.5f);
            float fpx = floorf(posx), fpy = floorf(posy);
            float wx = posx - fpx,    wy = posy - fpy;
            unsigned px0 = (unsigned)fpx, py0 = (unsigned)fpy;
            unsigned px1 = min(px0 + 1u, res - 1u);
            unsigned py1 = min(py0 + 1u, res - 1u);

            unsigned i00, i10, i01, i11;
            if (l < 11) {
                i00 = px0 + py0 * res;  i10 = px1 + py0 * res;
                i01 = px0 + py1 * res;  i11 = px1 + py1 * res;
            } else {
                unsigned hy0 = py0 * PRIME_Y, hy1 = py1 * PRIME_Y;
                i00 = (px0 ^ hy0) & HASH_MASK;  i10 = (px1 ^ hy0) & HASH_MASK;
                i01 = (px0 ^ hy1) & HASH_MASK;  i11 = (px1 ^ hy1) & HASH_MASK;
            }

            const float4* tb = (const float4*)table + ((size_t)l << 20);
            float4 f00 = __ldg(tb + i00);
            float4 f10 = __ldg(tb + i10);
            float4 f01 = __ldg(tb + i01);
            float4 f11 = __ldg(tb + i11);

            float w00 = (1.0f - wx) * (1.0f - wy);
            float w10 = wx * (1.0f - wy);
            float w01 = (1.0f - wx) * wy;
            float w11 = wx * wy;

            int k0 = l * 4;
            Er[pcol(k0 + 0)] = f2tf32(f00.x*w00 + f10.x*w10 + f01.x*w01 + f11.x*w11);
            Er[pcol(k0 + 1)] = f2tf32(f00.y*w00 + f10.y*w10 + f01.y*w01 + f11.y*w11);
            Er[pcol(k0 + 2)] = f2tf32(f00.z*w00 + f10.z*w10 + f01.z*w01 + f11.z*w11);
            Er[pcol(k0 + 3)] = f2tf32(f00.w*w00 + f10.w*w10 + f01.w*w01 + f11.w*w11);
        }
    }
    __syncthreads();

    // ---- Layer 1: each warp computes H1[:, warp*16 .. +16) ----
    {
        uint32_t Bf[2][6][2];
        #pragma unroll
        for (int nt = 0; nt < 2; nt++) {
            int n = warp * 16 + nt * 8 + g;
            #pragma unroll
            for (int kt = 0; kt < 6; kt++) {
                float2 v = *(const float2*)(W1s + n * W1_STRIDE + kt * 8 + 2 * t);
                Bf[nt][kt][0] = __float_as_uint(v.x);
                Bf[nt][kt][1] = __float_as_uint(v.y);
            }
        }
        float d[8][2][4];
        #pragma unroll
        for (int m = 0; m < 8; m++)
            #pragma unroll
            for (int nt = 0; nt < 2; nt++)
                d[m][nt][0] = d[m][nt][1] = d[m][nt][2] = d[m][nt][3] = 0.0f;

        #pragma unroll
        for (int kt = 0; kt < 6; kt++) {
            #pragma unroll
            for (int m = 0; m < 8; m++) {
                float2 va = *(const float2*)(E + (m*16 + g    ) * E_STRIDE + kt * 8 + 2 * t);
                float2 vb = *(const float2*)(E + (m*16 + g + 8) * E_STRIDE + kt * 8 + 2 * t);
                uint32_t a0 = __float_as_uint(va.x), a1 = __float_as_uint(vb.x);
                uint32_t a2 = __float_as_uint(va.y), a3 = __float_as_uint(vb.y);
                mma8(d[m][0][0], d[m][0][1], d[m][0][2], d[m][0][3],
                     a0, a1, a2, a3, Bf[0][kt][0], Bf[0][kt][1]);
                mma8(d[m][1][0], d[m][1][1], d[m][1][2], d[m][1][3],
                     a0, a1, a2, a3, Bf[1][kt][0], Bf[1][kt][1]);
            }
        }
        // ReLU + tf32 + store into H1 at PERMUTED k-cols (k index = neuron n)
        #pragma unroll
        for (int m = 0; m < 8; m++) {
            #pragma unroll
            for (int nt = 0; nt < 2; nt++) {
                int c0 = warp * 16 + nt * 8 + 2 * t;
                int c1 = c0 + 1;
                int r0 = m * 16 + g, r1 = r0 + 8;
                H1u[r0 * H1_STRIDE + pcol(c0)] = f2tf32(fmaxf(d[m][nt][0], 0.0f));
                H1u[r0 * H1_STRIDE + pcol(c1)] = f2tf32(fmaxf(d[m][nt][1], 0.0f));
                H1u[r1 * H1_STRIDE + pcol(c0)] = f2tf32(fmaxf(d[m][nt][2], 0.0f));
                H1u[r1 * H1_STRIDE + pcol(c1)] = f2tf32(fmaxf(d[m][nt][3], 0.0f));
            }
        }
    }
    __syncthreads();

    // ---- Layer 2: each warp computes H2[:, warp*16 .. +16), fused with w3 ----
    {
        uint32_t Bf[2][16][2];          // register-resident W2 slice
        #pragma unroll
        for (int nt = 0; nt < 2; nt++) {
            int n = warp * 16 + nt * 8 + g;
            #pragma unroll
            for (int kt = 0; kt < 16; kt++) {
                float2 v = *(const float2*)(W2s + n * W2_STRIDE + kt * 8 + 2 * t);
                Bf[nt][kt][0] = __float_as_uint(v.x);
                Bf[nt][kt][1] = __float_as_uint(v.y);
            }
        }
        float d[8][2][4];
        #pragma unroll
        for (int m = 0; m < 8; m++)
            #pragma unroll
            for (int nt = 0; nt < 2; nt++)
                d[m][nt][0] = d[m][nt][1] = d[m][nt][2] = d[m][nt][3] = 0.0f;

        #pragma unroll
        for (int kt = 0; kt < 16; kt++) {
            #pragma unroll
            for (int m = 0; m < 8; m++) {
                float2 va = *(const float2*)(H1 + (m*16 + g    ) * H1_STRIDE + kt * 8 + 2 * t);
                float2 vb = *(const float2*)(H1 + (m*16 + g + 8) * H1_STRIDE + kt * 8 + 2 * t);
                uint32_t a0 = __float_as_uint(va.x), a1 = __float_as_uint(vb.x);
                uint32_t a2 = __float_as_uint(va.y), a3 = __float_as_uint(vb.y);
                mma8(d[m][0][0], d[m][0][1], d[m][0][2], d[m][0][3],
                     a0, a1, a2, a3, Bf[0][kt][0], Bf[0][kt][1]);
                mma8(d[m][1][0], d[m][1][1], d[m][1][2], d[m][1][3],
                     a0, a1, a2, a3, Bf[1][kt][0], Bf[1][kt][1]);
            }
        }

        // Layer 3 partials: relu(H2) . w3 over this warp's 16 cols
        float w3c[2][2];
        #pragma unroll
        for (int nt = 0; nt < 2; nt++) {
            w3c[nt][0] = w3s[warp * 16 + nt * 8 + 2 * t];
            w3c[nt][1] = w3s[warp * 16 + nt * 8 + 2 * t + 1];
        }
        #pragma unroll
        for (int m = 0; m < 8; m++) {
            float p0 = fmaxf(d[m][0][0], 0.0f) * w3c[0][0]
                     + fmaxf(d[m][0][1], 0.0f) * w3c[0][1]
                     + fmaxf(d[m][1][0], 0.0f) * w3c[1][0]
                     + fmaxf(d[m][1][1], 0.0f) * w3c[1][1];
            float p1 = fmaxf(d[m][0][2], 0.0f) * w3c[0][0]
                     + fmaxf(d[m][0][3], 0.0f) * w3c[0][1]
                     + fmaxf(d[m][1][2], 0.0f) * w3c[1][0]
                     + fmaxf(d[m][1][3], 0.0f) * w3c[1][1];
            p0 += __shfl_xor_sync(0xFFFFFFFFu, p0, 1);
            p0 += __shfl_xor_sync(0xFFFFFFFFu, p0, 2);
            p1 += __shfl_xor_sync(0xFFFFFFFFu, p1, 1);
            p1 += __shfl_xor_sync(0xFFFFFFFFu, p1, 2);
            if (t == 0) {
                P[warp * 128 + m * 16 + g]     = p0;
                P[warp * 128 + m * 16 + g + 8] = p1;
            }
        }
    }
    __syncthreads();

    // ---- Cross-warp reduction + output ----
    if (tid < 128) {
        float s = 0.0f;
        #pragma unroll
        for (int w = 0; w < 8; w++) s += P[w * 128 + tid];
        out[blockIdx.x * 128 + tid] = s;
    }
}

extern "C" void kernel_launch(void* const* d_in, const int* in_sizes, int n_in,
                              void* d_out, int out_size)
{
    const float *table = nullptr, *w1 = nullptr, *w2 = nullptr, *w3 = nullptr;
    for (int i = 0; i < n_in; i++) {
        switch (in_sizes[i]) {
            case 50331648: table = (const float*)d_in[i]; break;
            case 6144:     w1    = (const float*)d_in[i]; break;
            case 16384:    w2    = (const float*)d_in[i]; break;
            case 128:      w3    = (const float*)d_in[i]; break;
            default: break;
        }
    }
    cudaFuncSetAttribute(tcnn_hmma_kernel,
                         cudaFuncAttributeMaxDynamicSharedMemorySize, SMEM_BYTES);
    tcnn_hmma_kernel<<<8192, 256, SMEM_BYTES>>>(table, w1, w2, w3, (float*)d_out);
}

// round 7
// speedup vs baseline: 3.7137x; 1.9770x over previous
#include <cuda_runtime.h>
#include <cstdint>

// TCNN_INR via mma.sync tf32 HMMA, persistent multi-tile CTAs.
// Grid 1024 x 256 thr; each CTA: stage weights once (fragment layouts), then
// 8 tiles of 128 pixels: enc -> E (row-major, pcol) -> L1 MMA -> H1 (fragment
// layout, STS.128/LDS.128 conflict-free via even/odd k-permutation) -> L2 MMA
// fused with w3 -> out.

#define PRIME_Y   2654435761u
#define HASH_MASK 0xFFFFFu

__constant__ float    c_scale[12] = {15.0f, 23.0f, 35.0f, 53.0f, 80.0f, 120.5f,
                                     181.25f, 272.375f, 409.0625f, 614.09375f,
                                     921.640625f, 1382.9609375f};
__constant__ unsigned c_res[12]   = {16u, 24u, 36u, 54u, 81u, 122u,
                                     183u, 274u, 411u, 616u, 923u, 1384u};

// k-interleave permutation within 8-groups for E storage: [0,4,1,5,2,6,3,7]
__device__ __forceinline__ int pcol(int k) {
    int j = k & 7;
    return (k & ~7) | ((j < 4) ? (j << 1) : (((j - 4) << 1) | 1));
}

__device__ __forceinline__ uint32_t f2tf32(float f) {
    uint32_t b;
    asm("cvt.rna.tf32.f32 %0, %1;" : "=r"(b) : "f"(f));
    return b;
}

__device__ __forceinline__ void mma8(float& d0, float& d1, float& d2, float& d3,
                                     uint32_t a0, uint32_t a1, uint32_t a2, uint32_t a3,
                                     uint32_t b0, uint32_t b1) {
    asm volatile("mma.sync.aligned.m16n8k8.row.col.f32.tf32.tf32.f32 "
                 "{%0,%1,%2,%3}, {%4,%5,%6,%7}, {%8,%9}, {%0,%1,%2,%3};"
                 : "+f"(d0), "+f"(d1), "+f"(d2), "+f"(d3)
                 : "r"(a0), "r"(a1), "r"(a2), "r"(a3), "r"(b0), "r"(b1));
}

// SMEM float offsets
#define E_STRIDE  50                          // gcd(18,32)=2 -> <=2-way conflicts
#define E_OFF     0
#define W1F_OFF   (E_OFF   + 128 * E_STRIDE)  // 6400
#define W2F_OFF   (W1F_OFF + 6144)            // 12544
#define H1F_OFF   (W2F_OFF + 16384)           // 28928
#define P_OFF     (H1F_OFF + 16384)           // 45312
#define W3_OFF    (P_OFF   + 1024)            // 46336
#define SMEM_FLOATS (W3_OFF + 128)            // 46464
#define SMEM_BYTES  (SMEM_FLOATS * 4)         // 185856

#define NUM_TILES 8

__global__ void __launch_bounds__(256, 1)
tcnn_hmma2_kernel(const float* __restrict__ table,
                  const float* __restrict__ w1,
                  const float* __restrict__ w2,
                  const float* __restrict__ w3,
                  float* __restrict__ out)
{
    extern __shared__ float sm[];
    float*    E    = sm + E_OFF;
    uint32_t* Eu   = (uint32_t*)E;
    uint32_t* W1f  = (uint32_t*)(sm + W1F_OFF);
    uint32_t* W2f  = (uint32_t*)(sm + W2F_OFF);
    uint32_t* H1f  = (uint32_t*)(sm + H1F_OFF);
    float*    P    = sm + P_OFF;
    float*    w3s  = sm + W3_OFF;

    const int tid  = threadIdx.x;
    const int lane = tid & 31;
    const int warp = tid >> 5;
    const int g    = lane >> 2;   // groupID
    const int t    = lane & 3;    // threadID_in_group

    // ---- Stage weights ONCE per CTA, directly in fragment layouts ----
    // W1f: [w][kt=6][nt=2][lane][2]; b-pair = (w1[kt*8+t][n], w1[kt*8+t+4][n])
    // (matches E's pcol storage: storage 2t -> logical t, 2t+1 -> logical t+4)
    #pragma unroll 4
    for (int idx = tid; idx < 6144; idx += 256) {
        int pair = idx & 1;
        int ln   = (idx >> 1) & 31;
        int nt   = (idx >> 6) & 1;
        int kt   = (idx >> 7) % 6;
        int w    = idx / 768;
        int gg = ln >> 2, tt = ln & 3;
        int k = kt * 8 + tt + pair * 4;
        int n = w * 16 + nt * 8 + gg;
        W1f[idx] = f2tf32(w1[k * 128 + n]);
    }
    // W2f: [w][kt=16][nt=2][lane][2]; b-pair = (w2[kt*8+2t][n], w2[kt*8+2t+1][n])
    // (matches H1f storage: even neurons -> slots 0-3, odd -> slots 4-7)
    #pragma unroll 4
    for (int idx = tid; idx < 16384; idx += 256) {
        int pair = idx & 1;
        int ln   = (idx >> 1) & 31;
        int nt   = (idx >> 6) & 1;
        int kt   = (idx >> 7) & 15;
        int w    = idx >> 11;
        int gg = ln >> 2, tt = ln & 3;
        int k = kt * 8 + 2 * tt + pair;
        int n = w * 16 + nt * 8 + gg;
        W2f[idx] = f2tf32(w2[k * 128 + n]);
    }
    if (tid < 128) w3s[tid] = w3[tid];

    // ---- Tile loop: 8 tiles of 128 pixels per CTA ----
    #pragma unroll 1
    for (int it = 0; it < NUM_TILES; it++) {
        const int tile = blockIdx.x * NUM_TILES + it;

        // ---- Hash encoding: 2 threads/pixel, 6 levels each -> E ----
        {
            const int   lp    = tid & 127;
            const int   lbase = (tid >> 7) * 6;
            const int   pix   = tile * 128 + lp;
            const float fx = (float)(pix & 1023) * (1.0f / 1023.0f);
            const float fy = (float)(pix >> 10)  * (1.0f / 1023.0f);
            uint32_t* Er = Eu + lp * E_STRIDE;

            #pragma unroll
            for (int li = 0; li < 6; li++) {
                const int      l   = lbase + li;
                const float    s   = c_scale[l];
                const unsigned res = c_res[l];
                float posx = fmaf(fx, s, 0.5f);
                float posy = fmaf(fy, s, 0.5f);
                float fpx = floorf(posx), fpy = floorf(posy);
                float wx = posx - fpx,    wy = posy - fpy;
                unsigned px0 = (unsigned)fpx, py0 = (unsigned)fpy;
                unsigned px1 = min(px0 + 1u, res - 1u);
                unsigned py1 = min(py0 + 1u, res - 1u);

                unsigned i00, i10, i01, i11;
                if (l < 11) {
                    i00 = px0 + py0 * res;  i10 = px1 + py0 * res;
                    i01 = px0 + py1 * res;  i11 = px1 + py1 * res;
                } else {
                    unsigned hy0 = py0 * PRIME_Y, hy1 = py1 * PRIME_Y;
                    i00 = (px0 ^ hy0) & HASH_MASK;  i10 = (px1 ^ hy0) & HASH_MASK;
                    i01 = (px0 ^ hy1) & HASH_MASK;  i11 = (px1 ^ hy1) & HASH_MASK;
                }

                const float4* tb = (const float4*)table + ((size_t)l << 20);
                float4 f00 = __ldg(tb + i00);
                float4 f10 = __ldg(tb + i10);
                float4 f01 = __ldg(tb + i01);
                float4 f11 = __ldg(tb + i11);

                float w00 = (1.0f - wx) * (1.0f - wy);
                float w10 = wx * (1.0f - wy);
                float w01 = (1.0f - wx) * wy;
                float w11 = wx * wy;

                int k0 = l * 4;
                Er[pcol(k0 + 0)] = f2tf32(f00.x*w00 + f10.x*w10 + f01.x*w01 + f11.x*w11);
                Er[pcol(k0 + 1)] = f2tf32(f00.y*w00 + f10.y*w10 + f01.y*w01 + f11.y*w11);
                Er[pcol(k0 + 2)] = f2tf32(f00.z*w00 + f10.z*w10 + f01.z*w01 + f11.z*w11);
                Er[pcol(k0 + 3)] = f2tf32(f00.w*w00 + f10.w*w10 + f01.w*w01 + f11.w*w11);
            }
        }
        __syncthreads();

        // ---- Layer 1: warp computes H1[:, warp*16..+16) -> H1f fragments ----
        {
            uint32_t Bf[2][6][2];
            #pragma unroll
            for (int nt = 0; nt < 2; nt++)
                #pragma unroll
                for (int kt = 0; kt < 6; kt++) {
                    uint2 v = *(const uint2*)(W1f + (((warp * 6 + kt) * 2 + nt) * 32 + lane) * 2);
                    Bf[nt][kt][0] = v.x;  Bf[nt][kt][1] = v.y;
                }

            float d[8][2][4];
            #pragma unroll
            for (int m = 0; m < 8; m++)
                #pragma unroll
                for (int nt = 0; nt < 2; nt++)
                    d[m][nt][0] = d[m][nt][1] = d[m][nt][2] = d[m][nt][3] = 0.0f;

            #pragma unroll
            for (int kt = 0; kt < 6; kt++) {
                #pragma unroll
                for (int m = 0; m < 8; m++) {
                    float2 va = *(const float2*)(E + (m*16 + g    ) * E_STRIDE + kt * 8 + 2 * t);
                    float2 vb = *(const float2*)(E + (m*16 + g + 8) * E_STRIDE + kt * 8 + 2 * t);
                    uint32_t a0 = __float_as_uint(va.x), a1 = __float_as_uint(vb.x);
                    uint32_t a2 = __float_as_uint(va.y), a3 = __float_as_uint(vb.y);
                    mma8(d[m][0][0], d[m][0][1], d[m][0][2], d[m][0][3],
                         a0, a1, a2, a3, Bf[0][kt][0], Bf[0][kt][1]);
                    mma8(d[m][1][0], d[m][1][1], d[m][1][2], d[m][1][3],
                         a0, a1, a2, a3, Bf[1][kt][0], Bf[1][kt][1]);
                }
            }

            // ReLU + tf32 -> H1f as one STS.128 per fragment (conflict-free).
            // Pack (d0, d2, d1, d3): consumer a0..a3 = (even-n row g, even-n row g+8,
            // odd-n row g, odd-n row g+8) for k-group kt = 2*warp + nt.
            #pragma unroll
            for (int m = 0; m < 8; m++) {
                #pragma unroll
                for (int nt = 0; nt < 2; nt++) {
                    int kt = 2 * warp + nt;
                    uint4 v;
                    v.x = f2tf32(fmaxf(d[m][nt][0], 0.0f));
                    v.y = f2tf32(fmaxf(d[m][nt][2], 0.0f));
                    v.z = f2tf32(fmaxf(d[m][nt][1], 0.0f));
                    v.w = f2tf32(fmaxf(d[m][nt][3], 0.0f));
                    *(uint4*)(H1f + ((m * 16 + kt) * 32 + lane) * 4) = v;
                }
            }
        }
        __syncthreads();

        // ---- Layer 2 (+w3 fusion): warp computes H2[:, warp*16..+16) ----
        {
            uint32_t Bf[2][16][2];
            #pragma unroll
            for (int nt = 0; nt < 2; nt++)
                #pragma unroll
                for (int kt = 0; kt < 16; kt++) {
                    uint2 v = *(const uint2*)(W2f + (((warp * 16 + kt) * 2 + nt) * 32 + lane) * 2);
                    Bf[nt][kt][0] = v.x;  Bf[nt][kt][1] = v.y;
                }

            float d[8][2][4];
            #pragma unroll
            for (int m = 0; m < 8; m++)
                #pragma unroll
                for (int nt = 0; nt < 2; nt++)
                    d[m][nt][0] = d[m][nt][1] = d[m][nt][2] = d[m][nt][3] = 0.0f;

            #pragma unroll
            for (int kt = 0; kt < 16; kt++) {
                #pragma unroll
                for (int m = 0; m < 8; m++) {
                    uint4 A = *(const uint4*)(H1f + ((m * 16 + kt) * 32 + lane) * 4);
                    mma8(d[m][0][0], d[m][0][1], d[m][0][2], d[m][0][3],
                         A.x, A.y, A.z, A.w, Bf[0][kt][0], Bf[0][kt][1]);
                    mma8(d[m][1][0], d[m][1][1], d[m][1][2], d[m][1][3],
                         A.x, A.y, A.z, A.w, Bf[1][kt][0], Bf[1][kt][1]);
                }
            }

            // Layer 3 partials: relu(H2) . w3 over this warp's 16 output cols
            float w3c[2][2];
            #pragma unroll
            for (int nt = 0; nt < 2; nt++) {
                w3c[nt][0] = w3s[warp * 16 + nt * 8 + 2 * t];
                w3c[nt][1] = w3s[warp * 16 + nt * 8 + 2 * t + 1];
            }
            #pragma unroll
            for (int m = 0; m < 8; m++) {
                float p0 = fmaxf(d[m][0][0], 0.0f) * w3c[0][0]
                         + fmaxf(d[m][0][1], 0.0f) * w3c[0][1]
                         + fmaxf(d[m][1][0], 0.0f) * w3c[1][0]
                         + fmaxf(d[m][1][1], 0.0f) * w3c[1][1];
                float p1 = fmaxf(d[m][0][2], 0.0f) * w3c[0][0]
                         + fmaxf(d[m][0][3], 0.0f) * w3c[0][1]
                         + fmaxf(d[m][1][2], 0.0f) * w3c[1][0]
                         + fmaxf(d[m][1][3], 0.0f) * w3c[1][1];
                p0 += __shfl_xor_sync(0xFFFFFFFFu, p0, 1);
                p0 += __shfl_xor_sync(0xFFFFFFFFu, p0, 2);
                p1 += __shfl_xor_sync(0xFFFFFFFFu, p1, 1);
                p1 += __shfl_xor_sync(0xFFFFFFFFu, p1, 2);
                if (t == 0) {
                    P[warp * 128 + m * 16 + g]     = p0;
                    P[warp * 128 + m * 16 + g + 8] = p1;
                }
            }
        }
        __syncthreads();

        // ---- Cross-warp reduction + output ----
        if (tid < 128) {
            float s = 0.0f;
            #pragma unroll
            for (int w = 0; w < 8; w++) s += P[w * 128 + tid];
            out[tile * 128 + tid] = s;
        }
    }
}

extern "C" void kernel_launch(void* const* d_in, const int* in_sizes, int n_in,
                              void* d_out, int out_size)
{
    const float *table = nullptr, *w1 = nullptr, *w2 = nullptr, *w3 = nullptr;
    for (int i = 0; i < n_in; i++) {
        switch (in_sizes[i]) {
            case 50331648: table = (const float*)d_in[i]; break;
            case 6144:     w1    = (const float*)d_in[i]; break;
            case 16384:    w2    = (const float*)d_in[i]; break;
            case 128:      w3    = (const float*)d_in[i]; break;
            default: break;
        }
    }
    cudaFuncSetAttribute(tcnn_hmma2_kernel,
                         cudaFuncAttributeMaxDynamicSharedMemorySize, SMEM_BYTES);
    tcnn_hmma2_kernel<<<1024, 256, SMEM_BYTES>>>(table, w1, w2, w3, (float*)d_out);
}

// round 8
// speedup vs baseline: 4.3862x; 1.1811x over previous
#include <cuda_runtime.h>
#include <cstdint>

// TCNN_INR via mma.sync tf32 HMMA, persistent multi-tile CTAs, 2D warp tiling.
// Grid 1024 x 256 thr; warp w = (mg = w>>2, nw = w&3) owns M-tiles mg*4..+4 and
// N-cols nw*32..+32 of each 128x128 layer output. Halves A-fragment SMEM
// traffic vs 1D-N tiling. H1 passes between layers in fragment-native layout
// (one STS.128 / LDS.128 per fragment, conflict-free).

#define PRIME_Y   2654435761u
#define HASH_MASK 0xFFFFFu

__constant__ float    c_scale[12] = {15.0f, 23.0f, 35.0f, 53.0f, 80.0f, 120.5f,
                                     181.25f, 272.375f, 409.0625f, 614.09375f,
                                     921.640625f, 1382.9609375f};
__constant__ unsigned c_res[12]   = {16u, 24u, 36u, 54u, 81u, 122u,
                                     183u, 274u, 411u, 616u, 923u, 1384u};

// k-interleave permutation within 8-groups for E storage: [0,4,1,5,2,6,3,7]
__device__ __forceinline__ int pcol(int k) {
    int j = k & 7;
    return (k & ~7) | ((j < 4) ? (j << 1) : (((j - 4) << 1) | 1));
}

__device__ __forceinline__ uint32_t f2tf32(float f) {
    uint32_t b;
    asm("cvt.rna.tf32.f32 %0, %1;" : "=r"(b) : "f"(f));
    return b;
}

__device__ __forceinline__ void mma8(float& d0, float& d1, float& d2, float& d3,
                                     uint32_t a0, uint32_t a1, uint32_t a2, uint32_t a3,
                                     uint32_t b0, uint32_t b1) {
    asm volatile("mma.sync.aligned.m16n8k8.row.col.f32.tf32.tf32.f32 "
                 "{%0,%1,%2,%3}, {%4,%5,%6,%7}, {%8,%9}, {%0,%1,%2,%3};"
                 : "+f"(d0), "+f"(d1), "+f"(d2), "+f"(d3)
                 : "r"(a0), "r"(a1), "r"(a2), "r"(a3), "r"(b0), "r"(b1));
}

// SMEM float offsets
#define E_STRIDE  50                          // gcd(18,32)=2 -> <=2-way conflicts
#define E_OFF     0
#define W1F_OFF   (E_OFF   + 128 * E_STRIDE)  // 6400
#define W2F_OFF   (W1F_OFF + 6144)            // 12544
#define H1F_OFF   (W2F_OFF + 16384)           // 28928
#define P_OFF     (H1F_OFF + 16384)           // 45312
#define W3_OFF    (P_OFF   + 512)             // 45824
#define SMEM_FLOATS (W3_OFF + 128)            // 45952
#define SMEM_BYTES  (SMEM_FLOATS * 4)         // 183808

#define NUM_TILES 8

__global__ void __launch_bounds__(256, 1)
tcnn_hmma3_kernel(const float* __restrict__ table,
                  const float* __restrict__ w1,
                  const float* __restrict__ w2,
                  const float* __restrict__ w3,
                  float* __restrict__ out)
{
    extern __shared__ float sm[];
    float*    E    = sm + E_OFF;
    uint32_t* Eu   = (uint32_t*)E;
    uint32_t* W1f  = (uint32_t*)(sm + W1F_OFF);
    uint32_t* W2f  = (uint32_t*)(sm + W2F_OFF);
    uint32_t* H1f  = (uint32_t*)(sm + H1F_OFF);
    float*    P    = sm + P_OFF;     // [128 rows][4 nw]
    float*    w3s  = sm + W3_OFF;

    const int tid  = threadIdx.x;
    const int lane = tid & 31;
    const int warp = tid >> 5;
    const int g    = lane >> 2;   // groupID
    const int t    = lane & 3;    // threadID_in_group
    const int mg   = warp >> 2;   // M-group (0..1): M-tiles mg*4..+4
    const int nw   = warp & 3;    // N-slice (0..3): cols nw*32..+32

    // ---- Stage weights ONCE per CTA, in fragment layouts ----
    // W1f: idx = nw*1536 + kt*256 + nt*64 + lane*2 + pair
    // b-pair = (w1[kt*8+t][n], w1[kt*8+t+4][n]) to match E's pcol storage
    #pragma unroll 4
    for (int idx = tid; idx < 6144; idx += 256) {
        int pair = idx & 1;
        int ln   = (idx >> 1) & 31;
        int nt   = (idx >> 6) & 3;
        int kt   = (idx >> 8) % 6;
        int nwi  = idx / 1536;
        int gg = ln >> 2, tt = ln & 3;
        int k = kt * 8 + tt + pair * 4;
        int n = nwi * 32 + nt * 8 + gg;
        W1f[idx] = f2tf32(w1[k * 128 + n]);
    }
    // W2f: idx = nw*4096 + kt*256 + nt*64 + lane*2 + pair
    // b-pair = (w2[kt*8+2t][n], w2[kt*8+2t+1][n]) to match H1f packing
    #pragma unroll 4
    for (int idx = tid; idx < 16384; idx += 256) {
        int pair = idx & 1;
        int ln   = (idx >> 1) & 31;
        int nt   = (idx >> 6) & 3;
        int kt   = (idx >> 8) & 15;
        int nwi  = idx >> 12;
        int gg = ln >> 2, tt = ln & 3;
        int k = kt * 8 + 2 * tt + pair;
        int n = nwi * 32 + nt * 8 + gg;
        W2f[idx] = f2tf32(w2[k * 128 + n]);
    }
    if (tid < 128) w3s[tid] = w3[tid];

    // ---- Tile loop ----
    #pragma unroll 1
    for (int it = 0; it < NUM_TILES; it++) {
        const int tile = blockIdx.x * NUM_TILES + it;

        // ---- Hash encoding: 2 threads/pixel, 6 levels each -> E ----
        {
            const int   lp    = tid & 127;
            const int   lbase = (tid >> 7) * 6;
            const int   pix   = tile * 128 + lp;
            const float fx = (float)(pix & 1023) * (1.0f / 1023.0f);
            const float fy = (float)(pix >> 10)  * (1.0f / 1023.0f);
            uint32_t* Er = Eu + lp * E_STRIDE;

            #pragma unroll
            for (int li = 0; li < 6; li++) {
                const int      l   = lbase + li;
                const float    s   = c_scale[l];
                const unsigned res = c_res[l];
                float posx = fmaf(fx, s, 0.5f);
                float posy = fmaf(fy, s, 0.5f);
                float fpx = floorf(posx), fpy = floorf(posy);
                float wx = posx - fpx,    wy = posy - fpy;
                unsigned px0 = (unsigned)fpx, py0 = (unsigned)fpy;
                unsigned px1 = min(px0 + 1u, res - 1u);
                unsigned py1 = min(py0 + 1u, res - 1u);

                unsigned i00, i10, i01, i11;
                if (l < 11) {
                    i00 = px0 + py0 * res;  i10 = px1 + py0 * res;
                    i01 = px0 + py1 * res;  i11 = px1 + py1 * res;
                } else {
                    unsigned hy0 = py0 * PRIME_Y, hy1 = py1 * PRIME_Y;
                    i00 = (px0 ^ hy0) & HASH_MASK;  i10 = (px1 ^ hy0) & HASH_MASK;
                    i01 = (px0 ^ hy1) & HASH_MASK;  i11 = (px1 ^ hy1) & HASH_MASK;
                }

                const float4* tb = (const float4*)table + ((size_t)l << 20);
                float4 f00 = __ldg(tb + i00);
                float4 f10 = __ldg(tb + i10);
                float4 f01 = __ldg(tb + i01);
                float4 f11 = __ldg(tb + i11);

                float w00 = (1.0f - wx) * (1.0f - wy);
                float w10 = wx * (1.0f - wy);
                float w01 = (1.0f - wx) * wy;
                float w11 = wx * wy;

                int k0 = l * 4;
                Er[pcol(k0 + 0)] = f2tf32(f00.x*w00 + f10.x*w10 + f01.x*w01 + f11.x*w11);
                Er[pcol(k0 + 1)] = f2tf32(f00.y*w00 + f10.y*w10 + f01.y*w01 + f11.y*w11);
                Er[pcol(k0 + 2)] = f2tf32(f00.z*w00 + f10.z*w10 + f01.z*w01 + f11.z*w11);
                Er[pcol(k0 + 3)] = f2tf32(f00.w*w00 + f10.w*w10 + f01.w*w01 + f11.w*w11);
            }
        }
        __syncthreads();

        // ---- Layer 1: warp computes H1[mg*64..+64, nw*32..+32) ----
        {
            uint32_t Bf[4][6][2];
            #pragma unroll
            for (int nt = 0; nt < 4; nt++)
                #pragma unroll
                for (int kt = 0; kt < 6; kt++) {
                    uint2 v = *(const uint2*)(W1f + (((nw * 6 + kt) * 4 + nt) * 32 + lane) * 2);
                    Bf[nt][kt][0] = v.x;  Bf[nt][kt][1] = v.y;
                }

            float d[4][4][4];
            #pragma unroll
            for (int mi = 0; mi < 4; mi++)
                #pragma unroll
                for (int nt = 0; nt < 4; nt++)
                    d[mi][nt][0] = d[mi][nt][1] = d[mi][nt][2] = d[mi][nt][3] = 0.0f;

            #pragma unroll
            for (int kt = 0; kt < 6; kt++) {
                #pragma unroll
                for (int mi = 0; mi < 4; mi++) {
                    int mt = mg * 4 + mi;
                    float2 va = *(const float2*)(E + (mt*16 + g    ) * E_STRIDE + kt * 8 + 2 * t);
                    float2 vb = *(const float2*)(E + (mt*16 + g + 8) * E_STRIDE + kt * 8 + 2 * t);
                    uint32_t a0 = __float_as_uint(va.x), a1 = __float_as_uint(vb.x);
                    uint32_t a2 = __float_as_uint(va.y), a3 = __float_as_uint(vb.y);
                    #pragma unroll
                    for (int nt = 0; nt < 4; nt++)
                        mma8(d[mi][nt][0], d[mi][nt][1], d[mi][nt][2], d[mi][nt][3],
                             a0, a1, a2, a3, Bf[nt][kt][0], Bf[nt][kt][1]);
                }
            }

            // ReLU + tf32 -> H1f, one STS.128 per fragment, (d0,d2,d1,d3) packing.
            // Fragment (m-tile mt, consumer kt_c = nw*4 + nt).
            #pragma unroll
            for (int mi = 0; mi < 4; mi++) {
                #pragma unroll
                for (int nt = 0; nt < 4; nt++) {
                    int mt  = mg * 4 + mi;
                    int ktc = nw * 4 + nt;
                    uint4 v;
                    v.x = f2tf32(fmaxf(d[mi][nt][0], 0.0f));
                    v.y = f2tf32(fmaxf(d[mi][nt][2], 0.0f));
                    v.z = f2tf32(fmaxf(d[mi][nt][1], 0.0f));
                    v.w = f2tf32(fmaxf(d[mi][nt][3], 0.0f));
                    *(uint4*)(H1f + ((mt * 16 + ktc) * 32 + lane) * 4) = v;
                }
            }
        }
        __syncthreads();

        // ---- Layer 2 (+w3 fusion): warp computes H2[mg*64..+64, nw*32..+32) ----
        {
            uint32_t Bf[4][16][2];
            #pragma unroll
            for (int nt = 0; nt < 4; nt++)
                #pragma unroll
                for (int kt = 0; kt < 16; kt++) {
                    uint2 v = *(const uint2*)(W2f + (((nw * 16 + kt) * 4 + nt) * 32 + lane) * 2);
                    Bf[nt][kt][0] = v.x;  Bf[nt][kt][1] = v.y;
                }

            float d[4][4][4];
            #pragma unroll
            for (int mi = 0; mi < 4; mi++)
                #pragma unroll
                for (int nt = 0; nt < 4; nt++)
                    d[mi][nt][0] = d[mi][nt][1] = d[mi][nt][2] = d[mi][nt][3] = 0.0f;

            #pragma unroll
            for (int kt = 0; kt < 16; kt++) {
                #pragma unroll
                for (int mi = 0; mi < 4; mi++) {
                    int mt = mg * 4 + mi;
                    uint4 A = *(const uint4*)(H1f + ((mt * 16 + kt) * 32 + lane) * 4);
                    #pragma unroll
                    for (int nt = 0; nt < 4; nt++)
                        mma8(d[mi][nt][0], d[mi][nt][1], d[mi][nt][2], d[mi][nt][3],
                             A.x, A.y, A.z, A.w, Bf[nt][kt][0], Bf[nt][kt][1]);
                }
            }

            // Layer 3 partials over this warp's 32 cols
            float w3c[4][2];
            #pragma unroll
            for (int nt = 0; nt < 4; nt++) {
                w3c[nt][0] = w3s[nw * 32 + nt * 8 + 2 * t];
                w3c[nt][1] = w3s[nw * 32 + nt * 8 + 2 * t + 1];
            }
            #pragma unroll
            for (int mi = 0; mi < 4; mi++) {
                float p0 = 0.0f, p1 = 0.0f;
                #pragma unroll
                for (int nt = 0; nt < 4; nt++) {
                    p0 += fmaxf(d[mi][nt][0], 0.0f) * w3c[nt][0]
                        + fmaxf(d[mi][nt][1], 0.0f) * w3c[nt][1];
                    p1 += fmaxf(d[mi][nt][2], 0.0f) * w3c[nt][0]
                        + fmaxf(d[mi][nt][3], 0.0f) * w3c[nt][1];
                }
                p0 += __shfl_xor_sync(0xFFFFFFFFu, p0, 1);
                p0 += __shfl_xor_sync(0xFFFFFFFFu, p0, 2);
                p1 += __shfl_xor_sync(0xFFFFFFFFu, p1, 1);
                p1 += __shfl_xor_sync(0xFFFFFFFFu, p1, 2);
                if (t == 0) {
                    int row0 = mg * 64 + mi * 16 + g;
                    P[(row0    ) * 4 + nw] = p0;
                    P[(row0 + 8) * 4 + nw] = p1;
                }
            }
        }
        __syncthreads();

        // ---- Cross-warp reduction (4 nw slices per row) + output ----
        if (tid < 128) {
            float4 v = *(const float4*)(P + tid * 4);
            out[tile * 128 + tid] = v.x + v.y + v.z + v.w;
        }
    }
}

extern "C" void kernel_launch(void* const* d_in, const int* in_sizes, int n_in,
                              void* d_out, int out_size)
{
    const float *table = nullptr, *w1 = nullptr, *w2 = nullptr, *w3 = nullptr;
    for (int i = 0; i < n_in; i++) {
        switch (in_sizes[i]) {
            case 50331648: table = (const float*)d_in[i]; break;
            case 6144:     w1    = (const float*)d_in[i]; break;
            case 16384:    w2    = (const float*)d_in[i]; break;
            case 128:      w3    = (const float*)d_in[i]; break;
            default: break;
        }
    }
    cudaFuncSetAttribute(tcnn_hmma3_kernel,
                         cudaFuncAttributeMaxDynamicSharedMemorySize, SMEM_BYTES);
    tcnn_hmma3_kernel<<<1024, 256, SMEM_BYTES>>>(table, w1, w2, w3, (float*)d_out);
}